// round 13
// baseline (speedup 1.0000x reference)
#include <cuda_runtime.h>
#include <cuda_bf16.h>
#include <cuda_fp16.h>
#include <cstdint>

#define NIMG 32
#define CDIM 512
#define TLEN 1024
#define NROWS (NIMG * TLEN)   // 32768
#define NB    2048

#define OFF_LOSS  16777216
#define OFF_PERP  16777217
#define OFF_NCB   16777218
#define OFF_SUM   (OFF_NCB + NB * CDIM)
#define OFF_CNT   (OFF_SUM + NB * CDIM)

#define MARGIN 16.0f
#define KSTAGE 6
#define A_PART 8192                     // 128 rows x 64B (32 bf16), swizzled
#define STAGE_BYTES 16384               // A + B
#define DSMEM (KSTAGE * STAGE_BYTES)    // 98304 -> 2 CTAs/SM

__device__ float          g_xf[NROWS * CDIM];   // x_flat fp32 [row][c]
__device__ __nv_bfloat16  g_xb[NROWS * CDIM];   // x_flat bf16
__device__ __nv_bfloat16  g_cbb[NB * CDIM];     // codebook bf16
__device__ __half         g_dist[(size_t)NROWS * NB];  // approx distances
__device__ float  g_tmin[(size_t)NROWS * 16];   // per-row per-128-tile min
__device__ int    g_idx[NROWS];
__device__ int    g_cnt[NB];
__device__ int    g_bstart[NB + 1];
__device__ int    g_bcur[NB];
__device__ int    g_blist[NROWS];
__device__ float  g_cnorm[NB];
__device__ double g_loss;

__device__ __forceinline__ unsigned long long packKey(float s, unsigned j) {
    unsigned u = __float_as_uint(s);
    u = (u & 0x80000000u) ? ~u : (u | 0x80000000u);
    return ((unsigned long long)u << 32) | j;
}
__device__ __forceinline__ float unpackS(unsigned long long key) {
    unsigned u = (unsigned)(key >> 32);
    u = (u & 0x80000000u) ? (u & 0x7FFFFFFFu) : ~u;
    return __uint_as_float(u);
}
__device__ __forceinline__ uint32_t smem_u32(const void* p) {
    uint32_t a;
    asm("{ .reg .u64 t; cvta.to.shared.u64 t, %1; cvt.u32.u64 %0, t; }" : "=r"(a) : "l"(p));
    return a;
}
#define CP_ASYNC16(sm, gp) \
    asm volatile("cp.async.cg.shared.global [%0], [%1], 16;" :: "r"(sm), "l"(gp))
#define CP_COMMIT() asm volatile("cp.async.commit_group;")
#define CP_WAIT2()  asm volatile("cp.async.wait_group 2;")
#define LDMX4(r0, r1, r2, r3, addr)                                           \
    asm volatile("ldmatrix.sync.aligned.m8n8.x4.shared.b16 {%0,%1,%2,%3}, [%4];" \
                 : "=r"(r0), "=r"(r1), "=r"(r2), "=r"(r3) : "r"(addr))
#define MMA16816(d, a, b)                                                     \
    asm volatile("mma.sync.aligned.m16n8k16.row.col.f32.bf16.bf16.f32 "       \
                 "{%0,%1,%2,%3}, {%4,%5,%6,%7}, {%8,%9}, {%0,%1,%2,%3};"      \
                 : "+f"((d)[0]), "+f"((d)[1]), "+f"((d)[2]), "+f"((d)[3])     \
                 : "r"((a)[0]), "r"((a)[1]), "r"((a)[2]), "r"((a)[3]),        \
                   "r"((b)[0]), "r"((b)[1]))

// ---------------------------------------------------------------------------
// fused: init + codebook row norms (exact fp32) + bf16 codebook copy
// ---------------------------------------------------------------------------
__global__ void k_cbprep(const float* __restrict__ cb) {
    int gi = blockIdx.x * 256 + threadIdx.x;
    if (gi < NB) g_cnt[gi] = 0;
    if (gi == 0) g_loss = 0.0;

    int warp = blockIdx.x * 8 + (threadIdx.x >> 5);
    int lane = threadIdx.x & 31;
    const float* row = cb + (size_t)warp * CDIM;
    __nv_bfloat16* brow = g_cbb + (size_t)warp * CDIM;
    float s = 0.0f;
#pragma unroll
    for (int i = 0; i < CDIM / 32; i++) {
        float v = row[lane + i * 32];
        s += v * v;
        brow[lane + i * 32] = __float2bfloat16(v);
    }
#pragma unroll
    for (int o = 16; o > 0; o >>= 1) s += __shfl_xor_sync(0xFFFFFFFFu, s, o);
    if (lane == 0) g_cnorm[warp] = s;
}

// transpose x [img][c][t] -> x_flat [row][c], fp32 + bf16, float4 path
__global__ void k_split(const float* __restrict__ x) {
    __shared__ float tile[32][33];
    const int tid = threadIdx.x;
    const int tx = tid & 7, ty = tid >> 3;
    const int t0 = blockIdx.x * 32, c0 = blockIdx.y * 32, img = blockIdx.z;

    float4 g = *(const float4*)&x[((size_t)img * CDIM + c0 + ty) * TLEN + t0 + tx * 4];
    tile[tx * 4 + 0][ty] = g.x;
    tile[tx * 4 + 1][ty] = g.y;
    tile[tx * 4 + 2][ty] = g.z;
    tile[tx * 4 + 3][ty] = g.w;
    __syncthreads();

    float4 v;
    v.x = tile[ty][tx * 4 + 0];
    v.y = tile[ty][tx * 4 + 1];
    v.z = tile[ty][tx * 4 + 2];
    v.w = tile[ty][tx * 4 + 3];
    size_t o = ((size_t)img * TLEN + t0 + ty) * CDIM + c0 + tx * 4;
    *(float4*)&g_xf[o] = v;
    __nv_bfloat162 b0 = {__float2bfloat16(v.x), __float2bfloat16(v.y)};
    __nv_bfloat162 b1 = {__float2bfloat16(v.z), __float2bfloat16(v.w)};
    *(__nv_bfloat162*)&g_xb[o]     = b0;
    *(__nv_bfloat162*)&g_xb[o + 2] = b1;
}

// ---------------------------------------------------------------------------
// bf16 HMMA GEMM, CTA 128x128, 256 threads, 6-stage cp.async, 64B pitch with
// XOR swizzle (seg' = seg ^ ((row>>1)&3)), barrier every 2 k-chunks.
// ---------------------------------------------------------------------------
__global__ __launch_bounds__(256, 2)
void k_dist() {
    extern __shared__ char dsm[];
    __shared__ float cnS[128];
    __shared__ float tminS[2][128];

    const int tid = threadIdx.x;
    const int warp = tid >> 5, lane = tid & 31;
    const int wm = warp & 3, wn = warp >> 2;
    const int m0 = blockIdx.y * 128, j0 = blockIdx.x * 128;

    if (tid < 128) cnS[tid] = g_cnorm[j0 + tid];

    // ---- loader (per-thread): rows lr, lr+64 for A and B, seg lq ----
    const int lr = tid >> 2, lq = tid & 3;
    const uint32_t dsmU = smem_u32(dsm);
    const int swzL = (lr >> 1) & 3;                 // same for lr and lr+64
    const uint32_t aOff0 = (uint32_t)(lr * 64        + ((lq ^ swzL) << 4));
    const uint32_t aOff1 = (uint32_t)((lr + 64) * 64 + ((lq ^ swzL) << 4));
    const __nv_bfloat16* gA0 = &g_xb[(size_t)(m0 + lr) * CDIM + lq * 8];
    const __nv_bfloat16* gB0 = &g_cbb[(size_t)(j0 + lr) * CDIM + lq * 8];

    auto issue = [&](int st, int kt) {
        uint32_t base = dsmU + st * STAGE_BYTES;
        CP_ASYNC16(base + aOff0,          gA0 + kt);
        CP_ASYNC16(base + aOff1,          gA0 + 64 * CDIM + kt);
        CP_ASYNC16(base + A_PART + aOff0, gB0 + kt);
        CP_ASYNC16(base + A_PART + aOff1, gB0 + 64 * CDIM + kt);
        CP_COMMIT();
    };

    float acc[2][8][4];
#pragma unroll
    for (int mt = 0; mt < 2; mt++)
#pragma unroll
        for (int nt = 0; nt < 8; nt++)
#pragma unroll
            for (int e = 0; e < 4; e++) acc[mt][nt][e] = 0.0f;

    // ---- per-warp/lane ldmatrix addressing (swizzled) ----
    // A: rows wm*32+mt*16+(lane&15); seg = ks*2 + (lane>>4)
    int rA[2];  uint32_t aBase[2]; int swzA[2];
#pragma unroll
    for (int mt = 0; mt < 2; mt++) {
        rA[mt] = wm * 32 + mt * 16 + (lane & 15);
        swzA[mt] = (rA[mt] >> 1) & 3;
        aBase[mt] = (uint32_t)(rA[mt] * 64);
    }
    const int sA0 = lane >> 4;                       // seg low bit base
    // B: rows wn*64 + p*16 + (g>>1)*8 + (lane&7); seg = ks*2 + (g&1)
    const int g = lane >> 3;
    int rB[4];  uint32_t bBase[4]; int swzB[4];
#pragma unroll
    for (int p = 0; p < 4; p++) {
        rB[p] = wn * 64 + p * 16 + (g >> 1) * 8 + (lane & 7);
        swzB[p] = (rB[p] >> 1) & 3;
        bBase[p] = (uint32_t)(A_PART + rB[p] * 64);
    }
    const int sB0 = g & 1;

    issue(0, 0); issue(1, 32); issue(2, 64); issue(3, 96);

    for (int ch = 0; ch < 16; ch += 2) {
        CP_WAIT2();                                   // chunks ch, ch+1 arrived
        __syncthreads();                              // publish + free ch-2, ch-1
        if (ch + 4 < 16) issue((ch + 4) % KSTAGE, (ch + 4) * 32);
        if (ch + 5 < 16) issue((ch + 5) % KSTAGE, (ch + 5) * 32);

#pragma unroll
        for (int sub = 0; sub < 2; sub++) {
            uint32_t base = dsmU + ((ch + sub) % KSTAGE) * STAGE_BYTES;
#pragma unroll
            for (int ks = 0; ks < 2; ks++) {
                uint32_t a[2][4], b[8][2];
#pragma unroll
                for (int mt = 0; mt < 2; mt++) {
                    int seg = ks * 2 + sA0;
                    LDMX4(a[mt][0], a[mt][1], a[mt][2], a[mt][3],
                          base + aBase[mt] + (uint32_t)(((seg ^ swzA[mt]) << 4)));
                }
#pragma unroll
                for (int p = 0; p < 4; p++) {
                    int seg = ks * 2 + sB0;
                    LDMX4(b[2 * p][0], b[2 * p][1], b[2 * p + 1][0], b[2 * p + 1][1],
                          base + bBase[p] + (uint32_t)(((seg ^ swzB[p]) << 4)));
                }
#pragma unroll
                for (int mt = 0; mt < 2; mt++)
#pragma unroll
                    for (int nt = 0; nt < 8; nt++)
                        MMA16816(acc[mt][nt], a[mt], b[nt]);
            }
        }
    }

    // epilogue: s = cnorm - 2*dot -> g_dist (fp16) + per-row tile min
#pragma unroll
    for (int mt = 0; mt < 2; mt++) {
        float rmin0 = 1e30f, rmin1 = 1e30f;
#pragma unroll
        for (int nt = 0; nt < 8; nt++) {
            int rr = m0 + wm * 32 + mt * 16 + (lane >> 2);
            int cc = wn * 64 + nt * 8 + (lane & 3) * 2;
            float s0 = cnS[cc]     - 2.0f * acc[mt][nt][0];
            float s1 = cnS[cc + 1] - 2.0f * acc[mt][nt][1];
            float s2 = cnS[cc]     - 2.0f * acc[mt][nt][2];
            float s3 = cnS[cc + 1] - 2.0f * acc[mt][nt][3];
            *(__half2*)&g_dist[(size_t)rr * NB + j0 + cc]       = __floats2half2_rn(s0, s1);
            *(__half2*)&g_dist[(size_t)(rr + 8) * NB + j0 + cc] = __floats2half2_rn(s2, s3);
            rmin0 = fminf(rmin0, fminf(s0, s1));
            rmin1 = fminf(rmin1, fminf(s2, s3));
        }
        rmin0 = fminf(rmin0, __shfl_xor_sync(0xFFFFFFFFu, rmin0, 1));
        rmin0 = fminf(rmin0, __shfl_xor_sync(0xFFFFFFFFu, rmin0, 2));
        rmin1 = fminf(rmin1, __shfl_xor_sync(0xFFFFFFFFu, rmin1, 1));
        rmin1 = fminf(rmin1, __shfl_xor_sync(0xFFFFFFFFu, rmin1, 2));
        if ((lane & 3) == 0) {
            tminS[wn][wm * 32 + mt * 16 + (lane >> 2)]     = rmin0;
            tminS[wn][wm * 32 + mt * 16 + 8 + (lane >> 2)] = rmin1;
        }
    }
    __syncthreads();
    if (tid < 128)
        g_tmin[(size_t)(m0 + tid) * 16 + blockIdx.x] =
            fminf(tminS[0][tid], tminS[1][tid]);
}

// ---------------------------------------------------------------------------
// candidate scan (tile-min pruned) + exact fp32 rescore + count + loss.
// ---------------------------------------------------------------------------
__global__ __launch_bounds__(256)
void k_cand(const float* __restrict__ cb) {
    __shared__ float lred[8];
    const int warp = threadIdx.x >> 5, lane = threadIdx.x & 31;
    const int row = blockIdx.x * 8 + warp;

    float tm = g_tmin[(size_t)row * 16 + (lane & 15)];
    float mn = tm;
#pragma unroll
    for (int o = 16; o > 0; o >>= 1) mn = fminf(mn, __shfl_xor_sync(0xFFFFFFFFu, mn, o));
    const float thr = mn + MARGIN;

    const float* xr = g_xf + (size_t)row * CDIM;
    // ||x||^2 via float4
    float xn = 0.0f;
    const float4* xr4 = (const float4*)xr;
#pragma unroll
    for (int q = 0; q < 4; q++) {
        float4 v4 = xr4[lane + q * 32];
        xn += v4.x * v4.x + v4.y * v4.y + v4.z * v4.z + v4.w * v4.w;
    }
#pragma unroll
    for (int o = 16; o > 0; o >>= 1) xn += __shfl_xor_sync(0xFFFFFFFFu, xn, o);

    unsigned long long best = 0xFFFFFFFFFFFFFFFFull;
#pragma unroll 1
    for (int t = 0; t < 16; t++) {
        float tmt = __shfl_sync(0xFFFFFFFFu, tm, t);
        if (tmt > thr) continue;
        const uint2* dp2 = (const uint2*)(g_dist + (size_t)row * NB + t * 128);
        uint2 v = dp2[lane];
        float2 fa = __half22float2(*(const __half2*)&v.x);
        float2 fb = __half22float2(*(const __half2*)&v.y);
        bool hit = fminf(fminf(fa.x, fa.y), fminf(fb.x, fb.y)) <= thr;
        unsigned m = __ballot_sync(0xFFFFFFFFu, hit);
        while (m) {
            int src = __ffs(m) - 1; m &= m - 1;
            unsigned vx = __shfl_sync(0xFFFFFFFFu, v.x, src);
            unsigned vy = __shfl_sync(0xFFFFFFFFu, v.y, src);
            int jb = t * 128 + src * 4;
            float2 ga = __half22float2(*(const __half2*)&vx);
            float2 gb = __half22float2(*(const __half2*)&vy);
            float gv[4] = {ga.x, ga.y, gb.x, gb.y};
#pragma unroll
            for (int q = 0; q < 4; q++) {
                if (gv[q] > thr) continue;
                int j = jb + q;
                const float* cr = cb + (size_t)j * CDIM;
                float d = 0.0f;
#pragma unroll
                for (int qq = 0; qq < 16; qq++)
                    d += xr[lane + qq * 32] * cr[lane + qq * 32];
#pragma unroll
                for (int o = 16; o > 0; o >>= 1) d += __shfl_xor_sync(0xFFFFFFFFu, d, o);
                float s = g_cnorm[j] - 2.0f * d;
                unsigned long long k = packKey(s, (unsigned)j);
                if (k < best) best = k;
            }
        }
    }
    if (lane == 0) {
        int idx = (int)(best & 0xFFFFFFFFu);
        g_idx[row] = idx;
        atomicAdd(&g_cnt[idx], 1);
        lred[warp] = xn + unpackS(best);
    }
    __syncthreads();
    if (threadIdx.x == 0) {
        float l = 0.0f;
#pragma unroll
        for (int i = 0; i < 8; i++) l += lred[i];
        atomicAdd(&g_loss, (double)l);
    }
}

// ---------------------------------------------------------------------------
// prefix scan over counts -> bucket offsets/cursors; fused perplexity
// ---------------------------------------------------------------------------
__global__ void k_prefix(float* __restrict__ out) {
    __shared__ int sh[1024];
    __shared__ double pr[1024];
    const int t = threadIdx.x;
    int c0 = g_cnt[2 * t], c1 = g_cnt[2 * t + 1];
    sh[t] = c0 + c1;
    {
        float p0 = (float)c0 / (32768.0f + 1e-10f);
        float p1 = (float)c1 / (32768.0f + 1e-10f);
        pr[t] = (double)(p0 * logf(p0 + 1e-7f)) + (double)(p1 * logf(p1 + 1e-7f));
    }
    __syncthreads();
#pragma unroll
    for (int o = 1; o < 1024; o <<= 1) {
        int add = (t >= o) ? sh[t - o] : 0;
        __syncthreads();
        sh[t] += add;
        __syncthreads();
    }
    int excl = (t == 0) ? 0 : sh[t - 1];
    g_bstart[2 * t]     = excl;
    g_bstart[2 * t + 1] = excl + c0;
    g_bcur[2 * t]       = excl;
    g_bcur[2 * t + 1]   = excl + c0;
    if (t == 1023) g_bstart[2048] = sh[1023];
    for (int o = 512; o > 0; o >>= 1) {
        if (t < o) pr[t] += pr[t + o];
        __syncthreads();
    }
    if (t == 0) out[OFF_PERP] = (float)exp(-pr[0]);
}

__global__ void k_fill() {
    int row = blockIdx.x * 256 + threadIdx.x;
    int idx = g_idx[row];
    int pos = atomicAdd(&g_bcur[idx], 1);
    g_blist[pos] = row;
}

// x_d_out gather-write only (transposed layout)
__global__ void k_out(const float* __restrict__ cb, float* __restrict__ out) {
    __shared__ int sidx[32];
    const int tid = threadIdx.x;
    const int r0 = blockIdx.x * 32;
    const int cbase = blockIdx.y * 128;
    const int img = r0 >> 10, t0 = r0 & 1023;

    if (tid < 32) sidx[tid] = g_idx[r0 + tid];
    __syncthreads();

    const int tt = tid & 31;
    const int c0 = cbase + (tid >> 5);
    const int idx = sidx[tt];
    const float* cbrow = cb + (size_t)idx * CDIM;
#pragma unroll
    for (int ci = 0; ci < 16; ci++) {
        int c = c0 + ci * 8;
        out[((size_t)img * CDIM + c) * TLEN + t0 + tt] = cbrow[c];
    }
}

// per-code segment sum (bucket gather) + EMA + reset; block 0 writes loss
__global__ __launch_bounds__(256)
void k_sum(const float* __restrict__ cs_in, const float* __restrict__ cc_in,
           float* __restrict__ sumR, float* __restrict__ cntR,
           float* __restrict__ ncb, float* __restrict__ out) {
    const int j = blockIdx.x;
    const int tid = threadIdx.x;
    const int s = g_bstart[j], e = g_bstart[j + 1];

    float a0 = 0.0f, a1 = 0.0f;
    for (int i = s; i < e; i++) {
        const float* xr = g_xf + (size_t)g_blist[i] * CDIM;
        a0 += xr[tid];
        a1 += xr[tid + 256];
    }
    float cnt = (float)(e - s);
    float cema = 0.99f * cc_in[j] + 0.01f * cnt;
    bool usage = (cema >= 1.0f);
    float denom = fmaxf(cema, 1e-10f);
    const float* xj = g_xf + (size_t)j * CDIM;

    float sema0 = 0.99f * cs_in[(size_t)j * CDIM + tid]       + 0.01f * a0;
    float sema1 = 0.99f * cs_in[(size_t)j * CDIM + tid + 256] + 0.01f * a1;
    sumR[(size_t)j * CDIM + tid]       = sema0;
    sumR[(size_t)j * CDIM + tid + 256] = sema1;
    ncb[(size_t)j * CDIM + tid]       = usage ? (sema0 / denom) : xj[tid];
    ncb[(size_t)j * CDIM + tid + 256] = usage ? (sema1 / denom) : xj[tid + 256];
    if (tid == 0) {
        cntR[j] = cema;
        if (j == 0) out[OFF_LOSS] = (float)(g_loss / (double)((size_t)NROWS * CDIM));
    }
}

// ---------------------------------------------------------------------------
extern "C" void kernel_launch(void* const* d_in, const int* in_sizes, int n_in,
                              void* d_out, int out_size) {
    const float* x  = (const float*)d_in[0];
    const float* cb = (const float*)d_in[1];
    const float* cs = (const float*)d_in[2];
    const float* cc = (const float*)d_in[3];
    float* out  = (float*)d_out;
    float* ncb  = out + OFF_NCB;
    float* sumR = out + OFF_SUM;
    float* cntR = out + OFF_CNT;

    cudaFuncSetAttribute(k_dist, cudaFuncAttributeMaxDynamicSharedMemorySize, DSMEM);

    k_cbprep<<<NB / 8, 256>>>(cb);
    k_split<<<dim3(TLEN / 32, CDIM / 32, NIMG), 256>>>(x);
    k_dist<<<dim3(NB / 128, NROWS / 128), 256, DSMEM>>>();
    k_cand<<<NROWS / 8, 256>>>(cb);
    k_prefix<<<1, 1024>>>(out);
    k_fill<<<NROWS / 256, 256>>>();
    dim3 go(NROWS / 32, CDIM / 128);
    k_out<<<go, 256>>>(cb, out);
    k_sum<<<NB, 256>>>(cs, cc, sumR, cntR, ncb, out);
}

// round 14
// speedup vs baseline: 1.0165x; 1.0165x over previous
#include <cuda_runtime.h>
#include <cuda_bf16.h>
#include <cuda_fp16.h>
#include <cstdint>

#define NIMG 32
#define CDIM 512
#define TLEN 1024
#define NROWS (NIMG * TLEN)   // 32768
#define NB    2048

#define OFF_LOSS  16777216
#define OFF_PERP  16777217
#define OFF_NCB   16777218
#define OFF_SUM   (OFF_NCB + NB * CDIM)
#define OFF_CNT   (OFF_SUM + NB * CDIM)

#define MARGIN 16.0f
#define KSTAGE 5
#define STAGE_BYTES 20480          // (A:128x40 + B:128x40) bf16, 80B pitch
#define DSMEM (KSTAGE * STAGE_BYTES)   // 102400

__device__ float          g_xf[NROWS * CDIM];   // x_flat fp32 [row][c]
__device__ __nv_bfloat16  g_xb[NROWS * CDIM];   // x_flat bf16
__device__ __nv_bfloat16  g_cbb[NB * CDIM];     // codebook bf16
__device__ __half         g_dist[(size_t)NROWS * NB];  // approx distances
__device__ float  g_tmin[(size_t)NROWS * 16];   // per-row per-128-tile min
__device__ int    g_idx[NROWS];
__device__ int    g_cnt[NB];
__device__ int    g_bstart[NB + 1];
__device__ int    g_bcur[NB];
__device__ int    g_blist[NROWS];
__device__ float  g_cnorm[NB];
__device__ double g_loss;

__device__ __forceinline__ unsigned long long packKey(float s, unsigned j) {
    unsigned u = __float_as_uint(s);
    u = (u & 0x80000000u) ? ~u : (u | 0x80000000u);
    return ((unsigned long long)u << 32) | j;
}
__device__ __forceinline__ float unpackS(unsigned long long key) {
    unsigned u = (unsigned)(key >> 32);
    u = (u & 0x80000000u) ? (u & 0x7FFFFFFFu) : ~u;
    return __uint_as_float(u);
}
__device__ __forceinline__ uint32_t smem_u32(const void* p) {
    uint32_t a;
    asm("{ .reg .u64 t; cvta.to.shared.u64 t, %1; cvt.u32.u64 %0, t; }" : "=r"(a) : "l"(p));
    return a;
}
#define CP_ASYNC16(sm, gp) \
    asm volatile("cp.async.cg.shared.global [%0], [%1], 16;" :: "r"(sm), "l"(gp))
#define CP_COMMIT() asm volatile("cp.async.commit_group;")
#define CP_WAIT3()  asm volatile("cp.async.wait_group 3;")
#define LDMX4(r0, r1, r2, r3, addr)                                           \
    asm volatile("ldmatrix.sync.aligned.m8n8.x4.shared.b16 {%0,%1,%2,%3}, [%4];" \
                 : "=r"(r0), "=r"(r1), "=r"(r2), "=r"(r3) : "r"(addr))
#define MMA16816(d, a, b)                                                     \
    asm volatile("mma.sync.aligned.m16n8k16.row.col.f32.bf16.bf16.f32 "       \
                 "{%0,%1,%2,%3}, {%4,%5,%6,%7}, {%8,%9}, {%0,%1,%2,%3};"      \
                 : "+f"((d)[0]), "+f"((d)[1]), "+f"((d)[2]), "+f"((d)[3])     \
                 : "r"((a)[0]), "r"((a)[1]), "r"((a)[2]), "r"((a)[3]),        \
                   "r"((b)[0]), "r"((b)[1]))

// ---------------------------------------------------------------------------
// fused: init + codebook row norms (exact fp32) + bf16 codebook copy
// ---------------------------------------------------------------------------
__global__ void k_cbprep(const float* __restrict__ cb) {
    int gi = blockIdx.x * 256 + threadIdx.x;
    if (gi < NB) g_cnt[gi] = 0;
    if (gi == 0) g_loss = 0.0;

    int warp = blockIdx.x * 8 + (threadIdx.x >> 5);
    int lane = threadIdx.x & 31;
    const float* row = cb + (size_t)warp * CDIM;
    __nv_bfloat16* brow = g_cbb + (size_t)warp * CDIM;
    float s = 0.0f;
#pragma unroll
    for (int i = 0; i < CDIM / 32; i++) {
        float v = row[lane + i * 32];
        s += v * v;
        brow[lane + i * 32] = __float2bfloat16(v);
    }
#pragma unroll
    for (int o = 16; o > 0; o >>= 1) s += __shfl_xor_sync(0xFFFFFFFFu, s, o);
    if (lane == 0) g_cnorm[warp] = s;
}

// transpose x [img][c][t] -> x_flat [row][c], fp32 + bf16, float4 path
__global__ void k_split(const float* __restrict__ x) {
    __shared__ float tile[32][33];
    const int tid = threadIdx.x;
    const int tx = tid & 7, ty = tid >> 3;
    const int t0 = blockIdx.x * 32, c0 = blockIdx.y * 32, img = blockIdx.z;

    float4 g = *(const float4*)&x[((size_t)img * CDIM + c0 + ty) * TLEN + t0 + tx * 4];
    tile[tx * 4 + 0][ty] = g.x;
    tile[tx * 4 + 1][ty] = g.y;
    tile[tx * 4 + 2][ty] = g.z;
    tile[tx * 4 + 3][ty] = g.w;
    __syncthreads();

    float4 v;
    v.x = tile[ty][tx * 4 + 0];
    v.y = tile[ty][tx * 4 + 1];
    v.z = tile[ty][tx * 4 + 2];
    v.w = tile[ty][tx * 4 + 3];
    size_t o = ((size_t)img * TLEN + t0 + ty) * CDIM + c0 + tx * 4;
    *(float4*)&g_xf[o] = v;
    __nv_bfloat162 b0 = {__float2bfloat16(v.x), __float2bfloat16(v.y)};
    __nv_bfloat162 b1 = {__float2bfloat16(v.z), __float2bfloat16(v.w)};
    *(__nv_bfloat162*)&g_xb[o]     = b0;
    *(__nv_bfloat162*)&g_xb[o + 2] = b1;
}

// ---------------------------------------------------------------------------
// bf16 HMMA GEMM, CTA 128x128, 256 threads, 5-stage cp.async + ldmatrix.
// (R12 measured-best version, unchanged.)
// ---------------------------------------------------------------------------
__global__ __launch_bounds__(256, 2)
void k_dist() {
    extern __shared__ char dsm[];
    __shared__ float cnS[128];
    __shared__ float tminS[2][128];

    const int tid = threadIdx.x;
    const int warp = tid >> 5, lane = tid & 31;
    const int wm = warp & 3, wn = warp >> 2;
    const int m0 = blockIdx.y * 128, j0 = blockIdx.x * 128;

    if (tid < 128) cnS[tid] = g_cnorm[j0 + tid];

    const int lr = tid >> 2, lq = tid & 3;
    const uint32_t smOff = (uint32_t)(lr * 80 + lq * 16);
    const uint32_t dsmU = smem_u32(dsm);
    const __nv_bfloat16* gA0 = &g_xb[(size_t)(m0 + lr) * CDIM + lq * 8];
    const __nv_bfloat16* gB0 = &g_cbb[(size_t)(j0 + lr) * CDIM + lq * 8];

    auto issue = [&](int st, int kt) {
        uint32_t base = dsmU + st * STAGE_BYTES + smOff;
        CP_ASYNC16(base,                 gA0 + kt);
        CP_ASYNC16(base + 64 * 80,       gA0 + 64 * CDIM + kt);
        CP_ASYNC16(base + 10240,         gB0 + kt);
        CP_ASYNC16(base + 10240 + 64*80, gB0 + 64 * CDIM + kt);
        CP_COMMIT();
    };

    float acc[2][8][4];
#pragma unroll
    for (int mt = 0; mt < 2; mt++)
#pragma unroll
        for (int nt = 0; nt < 8; nt++)
#pragma unroll
            for (int e = 0; e < 4; e++) acc[mt][nt][e] = 0.0f;

    issue(0, 0); issue(1, 32); issue(2, 64); issue(3, 96);
    const uint32_t aOff = (uint32_t)((wm * 32 + (lane & 15)) * 80 + (lane >> 4) * 16);
    const int gq = lane >> 3;
    const uint32_t bOff = (uint32_t)(10240 + (wn * 64 + (gq >> 1) * 8 + (lane & 7)) * 80
                                     + (gq & 1) * 16);

    for (int ch = 0; ch < 16; ch++) {
        CP_WAIT3();
        __syncthreads();
        if (ch + 4 < 16) issue((ch + 4) % KSTAGE, (ch + 4) * 32);

        uint32_t base = dsmU + (ch % KSTAGE) * STAGE_BYTES;
#pragma unroll
        for (int ks = 0; ks < 2; ks++) {
            uint32_t a[2][4], b[8][2];
#pragma unroll
            for (int mt = 0; mt < 2; mt++)
                LDMX4(a[mt][0], a[mt][1], a[mt][2], a[mt][3],
                      base + aOff + mt * (16 * 80) + ks * 32);
#pragma unroll
            for (int p = 0; p < 4; p++)
                LDMX4(b[2 * p][0], b[2 * p][1], b[2 * p + 1][0], b[2 * p + 1][1],
                      base + bOff + p * (16 * 80) + ks * 32);
#pragma unroll
            for (int mt = 0; mt < 2; mt++)
#pragma unroll
                for (int nt = 0; nt < 8; nt++)
                    MMA16816(acc[mt][nt], a[mt], b[nt]);
        }
    }

    // epilogue: s = cnorm - 2*dot -> g_dist (fp16) + per-row tile min
#pragma unroll
    for (int mt = 0; mt < 2; mt++) {
        float rmin0 = 1e30f, rmin1 = 1e30f;
#pragma unroll
        for (int nt = 0; nt < 8; nt++) {
            int rr = m0 + wm * 32 + mt * 16 + (lane >> 2);
            int cc = wn * 64 + nt * 8 + (lane & 3) * 2;
            float s0 = cnS[cc]     - 2.0f * acc[mt][nt][0];
            float s1 = cnS[cc + 1] - 2.0f * acc[mt][nt][1];
            float s2 = cnS[cc]     - 2.0f * acc[mt][nt][2];
            float s3 = cnS[cc + 1] - 2.0f * acc[mt][nt][3];
            *(__half2*)&g_dist[(size_t)rr * NB + j0 + cc]       = __floats2half2_rn(s0, s1);
            *(__half2*)&g_dist[(size_t)(rr + 8) * NB + j0 + cc] = __floats2half2_rn(s2, s3);
            rmin0 = fminf(rmin0, fminf(s0, s1));
            rmin1 = fminf(rmin1, fminf(s2, s3));
        }
        rmin0 = fminf(rmin0, __shfl_xor_sync(0xFFFFFFFFu, rmin0, 1));
        rmin0 = fminf(rmin0, __shfl_xor_sync(0xFFFFFFFFu, rmin0, 2));
        rmin1 = fminf(rmin1, __shfl_xor_sync(0xFFFFFFFFu, rmin1, 1));
        rmin1 = fminf(rmin1, __shfl_xor_sync(0xFFFFFFFFu, rmin1, 2));
        if ((lane & 3) == 0) {
            tminS[wn][wm * 32 + mt * 16 + (lane >> 2)]     = rmin0;
            tminS[wn][wm * 32 + mt * 16 + 8 + (lane >> 2)] = rmin1;
        }
    }
    __syncthreads();
    if (tid < 128)
        g_tmin[(size_t)(m0 + tid) * 16 + blockIdx.x] =
            fminf(tminS[0][tid], tminS[1][tid]);
}

// ---------------------------------------------------------------------------
// candidate scan (tile-min pruned) + exact fp32 rescore (float4) + count/loss
// ---------------------------------------------------------------------------
__global__ __launch_bounds__(256)
void k_cand(const float* __restrict__ cb) {
    __shared__ float lred[8];
    const int warp = threadIdx.x >> 5, lane = threadIdx.x & 31;
    const int row = blockIdx.x * 8 + warp;

    float tm = g_tmin[(size_t)row * 16 + (lane & 15)];
    float mn = tm;
#pragma unroll
    for (int o = 16; o > 0; o >>= 1) mn = fminf(mn, __shfl_xor_sync(0xFFFFFFFFu, mn, o));
    const float thr = mn + MARGIN;

    const float* xr = g_xf + (size_t)row * CDIM;
    const float4* xr4 = (const float4*)xr;
    // ||x||^2 and cached x fragments (float4 per lane x 4)
    float4 xv4[4];
    float xn = 0.0f;
#pragma unroll
    for (int q = 0; q < 4; q++) {
        xv4[q] = xr4[lane + q * 32];
        xn += xv4[q].x * xv4[q].x + xv4[q].y * xv4[q].y
            + xv4[q].z * xv4[q].z + xv4[q].w * xv4[q].w;
    }
#pragma unroll
    for (int o = 16; o > 0; o >>= 1) xn += __shfl_xor_sync(0xFFFFFFFFu, xn, o);

    unsigned long long best = 0xFFFFFFFFFFFFFFFFull;
#pragma unroll 1
    for (int t = 0; t < 16; t++) {
        float tmt = __shfl_sync(0xFFFFFFFFu, tm, t);
        if (tmt > thr) continue;
        const uint2* dp2 = (const uint2*)(g_dist + (size_t)row * NB + t * 128);
        uint2 v = dp2[lane];
        float2 fa = __half22float2(*(const __half2*)&v.x);
        float2 fb = __half22float2(*(const __half2*)&v.y);
        bool hit = fminf(fminf(fa.x, fa.y), fminf(fb.x, fb.y)) <= thr;
        unsigned m = __ballot_sync(0xFFFFFFFFu, hit);
        while (m) {
            int src = __ffs(m) - 1; m &= m - 1;
            unsigned vx = __shfl_sync(0xFFFFFFFFu, v.x, src);
            unsigned vy = __shfl_sync(0xFFFFFFFFu, v.y, src);
            int jb = t * 128 + src * 4;
            float2 ga = __half22float2(*(const __half2*)&vx);
            float2 gb = __half22float2(*(const __half2*)&vy);
            float gv[4] = {ga.x, ga.y, gb.x, gb.y};
#pragma unroll
            for (int q = 0; q < 4; q++) {
                if (gv[q] > thr) continue;
                int j = jb + q;
                const float4* cr4 = (const float4*)(cb + (size_t)j * CDIM);
                float d = 0.0f;
#pragma unroll
                for (int qq = 0; qq < 4; qq++) {
                    float4 c4 = cr4[lane + qq * 32];
                    d += xv4[qq].x * c4.x + xv4[qq].y * c4.y
                       + xv4[qq].z * c4.z + xv4[qq].w * c4.w;
                }
#pragma unroll
                for (int o = 16; o > 0; o >>= 1) d += __shfl_xor_sync(0xFFFFFFFFu, d, o);
                float s = g_cnorm[j] - 2.0f * d;
                unsigned long long k = packKey(s, (unsigned)j);
                if (k < best) best = k;
            }
        }
    }
    if (lane == 0) {
        int idx = (int)(best & 0xFFFFFFFFu);
        g_idx[row] = idx;
        atomicAdd(&g_cnt[idx], 1);
        lred[warp] = xn + unpackS(best);
    }
    __syncthreads();
    if (threadIdx.x == 0) {
        float l = 0.0f;
#pragma unroll
        for (int i = 0; i < 8; i++) l += lred[i];
        atomicAdd(&g_loss, (double)l);
    }
}

// ---------------------------------------------------------------------------
// prefix scan over counts -> bucket offsets/cursors; fused perplexity
// ---------------------------------------------------------------------------
__global__ void k_prefix(float* __restrict__ out) {
    __shared__ int sh[1024];
    __shared__ double pr[1024];
    const int t = threadIdx.x;
    int c0 = g_cnt[2 * t], c1 = g_cnt[2 * t + 1];
    sh[t] = c0 + c1;
    {
        float p0 = (float)c0 / (32768.0f + 1e-10f);
        float p1 = (float)c1 / (32768.0f + 1e-10f);
        pr[t] = (double)(p0 * logf(p0 + 1e-7f)) + (double)(p1 * logf(p1 + 1e-7f));
    }
    __syncthreads();
#pragma unroll
    for (int o = 1; o < 1024; o <<= 1) {
        int add = (t >= o) ? sh[t - o] : 0;
        __syncthreads();
        sh[t] += add;
        __syncthreads();
    }
    int excl = (t == 0) ? 0 : sh[t - 1];
    g_bstart[2 * t]     = excl;
    g_bstart[2 * t + 1] = excl + c0;
    g_bcur[2 * t]       = excl;
    g_bcur[2 * t + 1]   = excl + c0;
    if (t == 1023) g_bstart[2048] = sh[1023];
    for (int o = 512; o > 0; o >>= 1) {
        if (t < o) pr[t] += pr[t + o];
        __syncthreads();
    }
    if (t == 0) out[OFF_PERP] = (float)exp(-pr[0]);
}

__global__ void k_fill() {
    int row = blockIdx.x * 256 + threadIdx.x;
    int idx = g_idx[row];
    int pos = atomicAdd(&g_bcur[idx], 1);
    g_blist[pos] = row;
}

// x_d_out gather-write only (transposed layout)
__global__ void k_out(const float* __restrict__ cb, float* __restrict__ out) {
    __shared__ int sidx[32];
    const int tid = threadIdx.x;
    const int r0 = blockIdx.x * 32;
    const int cbase = blockIdx.y * 128;
    const int img = r0 >> 10, t0 = r0 & 1023;

    if (tid < 32) sidx[tid] = g_idx[r0 + tid];
    __syncthreads();

    const int tt = tid & 31;
    const int c0 = cbase + (tid >> 5);
    const int idx = sidx[tt];
    const float* cbrow = cb + (size_t)idx * CDIM;
#pragma unroll
    for (int ci = 0; ci < 16; ci++) {
        int c = c0 + ci * 8;
        out[((size_t)img * CDIM + c) * TLEN + t0 + tt] = cbrow[c];
    }
}

// per-code segment sum (bucket gather) + EMA + reset; block 0 writes loss
__global__ __launch_bounds__(256)
void k_sum(const float* __restrict__ cs_in, const float* __restrict__ cc_in,
           float* __restrict__ sumR, float* __restrict__ cntR,
           float* __restrict__ ncb, float* __restrict__ out) {
    const int j = blockIdx.x;
    const int tid = threadIdx.x;
    const int s = g_bstart[j], e = g_bstart[j + 1];

    float a0 = 0.0f, a1 = 0.0f;
    for (int i = s; i < e; i++) {
        const float* xr = g_xf + (size_t)g_blist[i] * CDIM;
        a0 += xr[tid];
        a1 += xr[tid + 256];
    }
    float cnt = (float)(e - s);
    float cema = 0.99f * cc_in[j] + 0.01f * cnt;
    bool usage = (cema >= 1.0f);
    float denom = fmaxf(cema, 1e-10f);
    const float* xj = g_xf + (size_t)j * CDIM;

    float sema0 = 0.99f * cs_in[(size_t)j * CDIM + tid]       + 0.01f * a0;
    float sema1 = 0.99f * cs_in[(size_t)j * CDIM + tid + 256] + 0.01f * a1;
    sumR[(size_t)j * CDIM + tid]       = sema0;
    sumR[(size_t)j * CDIM + tid + 256] = sema1;
    ncb[(size_t)j * CDIM + tid]       = usage ? (sema0 / denom) : xj[tid];
    ncb[(size_t)j * CDIM + tid + 256] = usage ? (sema1 / denom) : xj[tid + 256];
    if (tid == 0) {
        cntR[j] = cema;
        if (j == 0) out[OFF_LOSS] = (float)(g_loss / (double)((size_t)NROWS * CDIM));
    }
}

// ---------------------------------------------------------------------------
extern "C" void kernel_launch(void* const* d_in, const int* in_sizes, int n_in,
                              void* d_out, int out_size) {
    const float* x  = (const float*)d_in[0];
    const float* cb = (const float*)d_in[1];
    const float* cs = (const float*)d_in[2];
    const float* cc = (const float*)d_in[3];
    float* out  = (float*)d_out;
    float* ncb  = out + OFF_NCB;
    float* sumR = out + OFF_SUM;
    float* cntR = out + OFF_CNT;

    cudaFuncSetAttribute(k_dist, cudaFuncAttributeMaxDynamicSharedMemorySize, DSMEM);

    k_cbprep<<<NB / 8, 256>>>(cb);
    k_split<<<dim3(TLEN / 32, CDIM / 32, NIMG), 256>>>(x);
    k_dist<<<dim3(NB / 128, NROWS / 128), 256, DSMEM>>>();
    k_cand<<<NROWS / 8, 256>>>(cb);
    k_prefix<<<1, 1024>>>(out);
    k_fill<<<NROWS / 256, 256>>>();
    dim3 go(NROWS / 32, CDIM / 128);
    k_out<<<go, 256>>>(cb, out);
    k_sum<<<NB, 256>>>(cs, cc, sumR, cntR, ncb, out);
}